// round 2
// baseline (speedup 1.0000x reference)
#include <cuda_runtime.h>

// LocalAttender fused kernel for GB300 (sm_103a) — Round 2.
// Shapes (fixed): guide [8,128,128,128] f32, value [8,128,64,64] f32,
//                 w_conv [9,128] f32, b_conv [9] f32, out [8,128,128,128] f32.
//
// One thread <-> one value-resolution "quad" (2x2 output pixels), packed
// f32x2 math (component0 = output col 2w, component1 = col 2w+1).
//
// R2 change vs R1: grid 512 -> 1024 (block = (b, h, quad-set of 32 cols)),
// 4-way channel split per block (32 ch/warp) to halve per-thread work and
// raise resident blocks/SM (latency-bound at occ=21% in R1).
//
// Block = 128 threads = 4 warps, all on the same 32-quad set:
//   warp w: channels [32w, 32w+32)
// Grid = B*H*2 = 1024 blocks.

#define K9 9
#define CIN 128
#define HV 64
#define WV 64
#define HO 128
#define WO 128
#define CPW 32   // channels per warp

__device__ __forceinline__ unsigned long long pk2(float lo, float hi) {
    unsigned long long d;
    asm("mov.b64 %0, {%1,%2};" : "=l"(d) : "f"(lo), "f"(hi));
    return d;
}
__device__ __forceinline__ void upk2(unsigned long long v, float& lo, float& hi) {
    asm("mov.b64 {%0,%1}, %2;" : "=f"(lo), "=f"(hi) : "l"(v));
}
__device__ __forceinline__ unsigned long long fma2(unsigned long long a,
                                                   unsigned long long b,
                                                   unsigned long long c) {
    unsigned long long d;
    asm("fma.rn.f32x2 %0, %1, %2, %3;" : "=l"(d) : "l"(a), "l"(b), "l"(c));
    return d;
}
__device__ __forceinline__ unsigned long long add2(unsigned long long a,
                                                   unsigned long long b) {
    unsigned long long d;
    asm("add.rn.f32x2 %0, %1, %2;" : "=l"(d) : "l"(a), "l"(b));
    return d;
}

__device__ __forceinline__ void softmax9(float a[K9]) {
    float m = a[0];
#pragma unroll
    for (int k = 1; k < K9; ++k) m = fmaxf(m, a[k]);
    float s = 0.0f;
#pragma unroll
    for (int k = 0; k < K9; ++k) { a[k] = __expf(a[k] - m); s += a[k]; }
    float inv = 1.0f / s;
#pragma unroll
    for (int k = 0; k < K9; ++k) a[k] *= inv;
}

__global__ __launch_bounds__(128, 6)
void la_fused_kernel(const float* __restrict__ guide,
                     const float* __restrict__ value,
                     const float* __restrict__ wconv,
                     const float* __restrict__ bconv,
                     float* __restrict__ out) {
    // pre-packed (w,w) pairs, [c][k] so the per-c inner loop is contiguous
    __shared__ unsigned long long w2_s[CIN * K9];          // 9216 B
    __shared__ float b_s[K9];
    __shared__ unsigned long long part[4][32][2 * K9 + 1]; // 19456 B

    const int tid  = threadIdx.x;
    const int warp = tid >> 5;
    const int lane = tid & 31;

    // ---- phase 0: stage weights ----
    for (int i = tid; i < CIN * K9; i += 128) {
        int k = i / CIN, c = i - k * CIN;
        float v = wconv[i];
        w2_s[c * K9 + k] = pk2(v, v);
    }
    if (tid < K9) b_s[tid] = bconv[tid];
    __syncthreads();

    const int b     = blockIdx.x >> 7;
    const int h     = (blockIdx.x >> 1) & 63;
    const int set   = blockIdx.x & 1;
    const int wq    = (set << 5) + lane;   // value col 0..63
    const int cbase = warp * CPW;          // channel quarter

    unsigned long long acc[K9][2];
#pragma unroll
    for (int k = 0; k < K9; ++k) { acc[k][0] = 0ull; acc[k][1] = 0ull; }

    // ---- phase 1: att partial = sum_c w[k,c] * guide (+ residual for c<9) ----
    // guide pixel pair (2h, 2wq..2wq+1) loaded as one 64-bit word per row.
    const float* gp = guide + ((b * CIN + cbase) * HO + 2 * h) * WO + 2 * wq;
    const int GCS = HO * WO; // 16384, channel stride

    if (warp == 0) {
        // first 9 channels also contribute the residual guide[:, :9]
#pragma unroll
        for (int c = 0; c < K9; ++c) {
            unsigned long long G0 = *(const unsigned long long*)(gp + c * GCS);
            unsigned long long G1 = *(const unsigned long long*)(gp + c * GCS + WO);
#pragma unroll
            for (int k = 0; k < K9; ++k) {
                unsigned long long W = w2_s[c * K9 + k];
                acc[k][0] = fma2(G0, W, acc[k][0]);
                acc[k][1] = fma2(G1, W, acc[k][1]);
            }
            acc[c][0] = add2(acc[c][0], G0);
            acc[c][1] = add2(acc[c][1], G1);
        }
#pragma unroll 4
        for (int c = K9; c < CPW; ++c) {
            unsigned long long G0 = *(const unsigned long long*)(gp + c * GCS);
            unsigned long long G1 = *(const unsigned long long*)(gp + c * GCS + WO);
#pragma unroll
            for (int k = 0; k < K9; ++k) {
                unsigned long long W = w2_s[c * K9 + k];
                acc[k][0] = fma2(G0, W, acc[k][0]);
                acc[k][1] = fma2(G1, W, acc[k][1]);
            }
        }
    } else {
#pragma unroll 4
        for (int c = 0; c < CPW; ++c) {
            unsigned long long G0 = *(const unsigned long long*)(gp + c * GCS);
            unsigned long long G1 = *(const unsigned long long*)(gp + c * GCS + WO);
#pragma unroll
            for (int k = 0; k < K9; ++k) {
                unsigned long long W = w2_s[(cbase + c) * K9 + k];
                acc[k][0] = fma2(G0, W, acc[k][0]);
                acc[k][1] = fma2(G1, W, acc[k][1]);
            }
        }
    }

    // ---- phase 1b: 4-way all-reduce of the channel quarters ----
#pragma unroll
    for (int k = 0; k < K9; ++k) {
        part[warp][lane][2 * k]     = acc[k][0];
        part[warp][lane][2 * k + 1] = acc[k][1];
    }
    __syncthreads();
#pragma unroll
    for (int pw = 1; pw < 4; ++pw) {
        const int peer = warp ^ pw;
#pragma unroll
        for (int k = 0; k < K9; ++k) {
            acc[k][0] = add2(acc[k][0], part[peer][lane][2 * k]);
            acc[k][1] = add2(acc[k][1], part[peer][lane][2 * k + 1]);
        }
    }

    // bias
#pragma unroll
    for (int k = 0; k < K9; ++k) {
        unsigned long long B = pk2(b_s[k], b_s[k]);
        acc[k][0] = add2(acc[k][0], B);
        acc[k][1] = add2(acc[k][1], B);
    }

    // ---- phase 2: softmax over k for each of the 4 quad pixels ----
#pragma unroll
    for (int r = 0; r < 2; ++r) {
        float a0[K9], a1[K9];
#pragma unroll
        for (int k = 0; k < K9; ++k) upk2(acc[k][r], a0[k], a1[k]);
        softmax9(a0);
        softmax9(a1);
#pragma unroll
        for (int k = 0; k < K9; ++k) acc[k][r] = pk2(a0[k], a1[k]);
    }

    // ---- phase 3: gather-weight-store over this warp's 32 channels ----
    const int ym1 = (h == 0) ? 0 : h - 1;
    const int yp1 = (h == HV - 1) ? HV - 1 : h + 1;
    const int xm1 = (wq == 0) ? 0 : wq - 1;
    const int xp1 = (wq == WV - 1) ? WV - 1 : wq + 1;
    const int ro[3] = { ym1 * WV, h * WV, yp1 * WV };
    const int co[3] = { xm1, wq, xp1 };

    const float* vp = value + (b * CIN + cbase) * (HV * WV);
    float* op = out + ((b * CIN + cbase) * HO + 2 * h) * WO + 2 * wq;
    const int VCS = HV * WV; // 4096

#pragma unroll 4
    for (int c = 0; c < CPW; ++c) {
        const float* v = vp + c * VCS;
        unsigned long long o0 = 0ull, o1 = 0ull;
#pragma unroll
        for (int dy = 0; dy < 3; ++dy) {
#pragma unroll
            for (int dx = 0; dx < 3; ++dx) {
                float nv = __ldg(v + ro[dy] + co[dx]);
                unsigned long long NV = pk2(nv, nv);
                const int k = dy * 3 + dx;
                o0 = fma2(acc[k][0], NV, o0);
                o1 = fma2(acc[k][1], NV, o1);
            }
        }
        *(unsigned long long*)(op + c * GCS)      = o0;
        *(unsigned long long*)(op + c * GCS + WO) = o1;
    }
}

extern "C" void kernel_launch(void* const* d_in, const int* in_sizes, int n_in,
                              void* d_out, int out_size) {
    const float* guide = (const float*)d_in[0];
    const float* value = (const float*)d_in[1];
    const float* wconv = (const float*)d_in[2];
    const float* bconv = (const float*)d_in[3];
    float* out = (float*)d_out;
    (void)in_sizes; (void)n_in; (void)out_size;

    la_fused_kernel<<<1024, 128>>>(guide, value, wconv, bconv, out);
}

// round 3
// speedup vs baseline: 1.1072x; 1.1072x over previous
#include <cuda_runtime.h>

// LocalAttender — Round 3: two-kernel split.
// Shapes (fixed): guide [8,128,128,128] f32, value [8,128,64,64] f32,
//                 w_conv [9,128] f32, b_conv [9] f32, out [8,128,128,128] f32.
//
// Kernel A computes softmaxed att per 2x2 output quad (packed f32x2 over the
// two output columns) into a __device__ scratch (4.7 MB), layout
// g_att[b][h][set][2k+r][lane] for coalesced store/load.
// Kernel B is embarrassingly parallel over channels: stages the 32-quad att
// block to smem, then gather-weight-store, 8 channels per thread.

#define K9 9
#define CIN 128
#define HV 64
#define WV 64
#define HO 128
#define WO 128

typedef unsigned long long u64;

__device__ u64 g_att[8][64][2][2 * K9][32];   // 4.7 MB scratch

__device__ __forceinline__ u64 pk2(float lo, float hi) {
    u64 d; asm("mov.b64 %0, {%1,%2};" : "=l"(d) : "f"(lo), "f"(hi)); return d;
}
__device__ __forceinline__ void upk2(u64 v, float& lo, float& hi) {
    asm("mov.b64 {%0,%1}, %2;" : "=f"(lo), "=f"(hi) : "l"(v));
}
__device__ __forceinline__ u64 fma2(u64 a, u64 b, u64 c) {
    u64 d; asm("fma.rn.f32x2 %0, %1, %2, %3;" : "=l"(d) : "l"(a), "l"(b), "l"(c)); return d;
}
__device__ __forceinline__ u64 add2(u64 a, u64 b) {
    u64 d; asm("add.rn.f32x2 %0, %1, %2;" : "=l"(d) : "l"(a), "l"(b)); return d;
}

__device__ __forceinline__ void softmax9(float a[K9]) {
    float m = a[0];
#pragma unroll
    for (int k = 1; k < K9; ++k) m = fmaxf(m, a[k]);
    float s = 0.0f;
#pragma unroll
    for (int k = 0; k < K9; ++k) { a[k] = __expf(a[k] - m); s += a[k]; }
    float inv = 1.0f / s;
#pragma unroll
    for (int k = 0; k < K9; ++k) a[k] *= inv;
}

// ---------------------------------------------------------------------------
// Kernel A: att.  Grid = B*H*2 = 1024 blocks, 128 threads.
// Block = (b, h, quad-set of 32 cols); 4 warps = 4-way channel split (32 ch).
// ---------------------------------------------------------------------------
__global__ __launch_bounds__(128, 6)
void la_att_kernel(const float* __restrict__ guide,
                   const float* __restrict__ wconv,
                   const float* __restrict__ bconv) {
    __shared__ u64 w2_s[CIN * K9];             // packed (w,w), [c][k]
    __shared__ float b_s[K9];
    __shared__ u64 part[4][32][2 * K9 + 1];

    const int tid  = threadIdx.x;
    const int warp = tid >> 5;
    const int lane = tid & 31;

    // stage weights (k = i>>7, c = i&127 : shift/and only)
    for (int i = tid; i < CIN * K9; i += 128) {
        int k = i >> 7, c = i & (CIN - 1);
        float v = wconv[i];
        w2_s[c * K9 + k] = pk2(v, v);
    }
    if (tid < K9) b_s[tid] = bconv[tid];
    __syncthreads();

    const int b     = blockIdx.x >> 7;
    const int h     = (blockIdx.x >> 1) & 63;
    const int set   = blockIdx.x & 1;
    const int wq    = (set << 5) + lane;       // value col
    const int cbase = warp << 5;               // 32 channels per warp

    u64 acc[K9][2];
#pragma unroll
    for (int k = 0; k < K9; ++k) { acc[k][0] = 0ull; acc[k][1] = 0ull; }

    const float* gp = guide + ((b * CIN + cbase) * HO + 2 * h) * WO + 2 * wq;
    const int GCS = HO * WO;                   // 16384

    if (warp == 0) {
#pragma unroll
        for (int c = 0; c < K9; ++c) {
            u64 G0 = *(const u64*)(gp + c * GCS);
            u64 G1 = *(const u64*)(gp + c * GCS + WO);
#pragma unroll
            for (int k = 0; k < K9; ++k) {
                u64 W = w2_s[c * K9 + k];
                acc[k][0] = fma2(G0, W, acc[k][0]);
                acc[k][1] = fma2(G1, W, acc[k][1]);
            }
            acc[c][0] = add2(acc[c][0], G0);   // residual guide[:, :9]
            acc[c][1] = add2(acc[c][1], G1);
        }
#pragma unroll 4
        for (int c = K9; c < 32; ++c) {
            u64 G0 = *(const u64*)(gp + c * GCS);
            u64 G1 = *(const u64*)(gp + c * GCS + WO);
#pragma unroll
            for (int k = 0; k < K9; ++k) {
                u64 W = w2_s[c * K9 + k];
                acc[k][0] = fma2(G0, W, acc[k][0]);
                acc[k][1] = fma2(G1, W, acc[k][1]);
            }
        }
    } else {
#pragma unroll 4
        for (int c = 0; c < 32; ++c) {
            u64 G0 = *(const u64*)(gp + c * GCS);
            u64 G1 = *(const u64*)(gp + c * GCS + WO);
#pragma unroll
            for (int k = 0; k < K9; ++k) {
                u64 W = w2_s[(cbase + c) * K9 + k];
                acc[k][0] = fma2(G0, W, acc[k][0]);
                acc[k][1] = fma2(G1, W, acc[k][1]);
            }
        }
    }

    // 4-way symmetric all-reduce
#pragma unroll
    for (int k = 0; k < K9; ++k) {
        part[warp][lane][2 * k]     = acc[k][0];
        part[warp][lane][2 * k + 1] = acc[k][1];
    }
    __syncthreads();
#pragma unroll
    for (int pw = 1; pw < 4; ++pw) {
        const int peer = warp ^ pw;
#pragma unroll
        for (int k = 0; k < K9; ++k) {
            acc[k][0] = add2(acc[k][0], part[peer][lane][2 * k]);
            acc[k][1] = add2(acc[k][1], part[peer][lane][2 * k + 1]);
        }
    }

    if (warp == 0) {
        // bias + softmax + store (other warps done)
#pragma unroll
        for (int k = 0; k < K9; ++k) {
            u64 B = pk2(b_s[k], b_s[k]);
            acc[k][0] = add2(acc[k][0], B);
            acc[k][1] = add2(acc[k][1], B);
        }
#pragma unroll
        for (int r = 0; r < 2; ++r) {
            float a0[K9], a1[K9];
#pragma unroll
            for (int k = 0; k < K9; ++k) upk2(acc[k][r], a0[k], a1[k]);
            softmax9(a0);
            softmax9(a1);
#pragma unroll
            for (int k = 0; k < K9; ++k) acc[k][r] = pk2(a0[k], a1[k]);
        }
#pragma unroll
        for (int k = 0; k < K9; ++k) {
            g_att[b][h][set][2 * k][lane]     = acc[k][0];
            g_att[b][h][set][2 * k + 1][lane] = acc[k][1];
        }
    }
}

// ---------------------------------------------------------------------------
// Kernel B: output.  Grid = B*H*2*4 = 4096 blocks, 128 threads.
// Block = (b, h, set, channel-group of 32); warp w: channels [8w, 8w+8).
// ---------------------------------------------------------------------------
__global__ __launch_bounds__(128, 6)
void la_out_kernel(const float* __restrict__ value,
                   float* __restrict__ out) {
    __shared__ u64 att_s[2 * K9 * 32];         // 4608 B

    const int tid  = threadIdx.x;
    const int warp = tid >> 5;
    const int lane = tid & 31;

    const int cg  = blockIdx.x & 3;
    const int set = (blockIdx.x >> 2) & 1;
    const int h   = (blockIdx.x >> 3) & 63;
    const int b   = blockIdx.x >> 9;

    // stage this block's att (576 u64, coalesced)
    {
        const u64* reg = &g_att[b][h][set][0][0];
        for (int i = tid; i < 2 * K9 * 32; i += 128) att_s[i] = reg[i];
    }
    __syncthreads();

    const int wq    = (set << 5) + lane;
    const int cbase = (cg << 5) + (warp << 3); // 8 channels per thread

    u64 acc[K9][2];
#pragma unroll
    for (int k = 0; k < K9; ++k) {
        acc[k][0] = att_s[(2 * k) * 32 + lane];
        acc[k][1] = att_s[(2 * k + 1) * 32 + lane];
    }

    const int ym1 = (h == 0) ? 0 : h - 1;
    const int yp1 = (h == HV - 1) ? HV - 1 : h + 1;
    const int xm1 = (wq == 0) ? 0 : wq - 1;
    const int xp1 = (wq == WV - 1) ? WV - 1 : wq + 1;
    const int ro[3] = { ym1 * WV, h * WV, yp1 * WV };
    const int co[3] = { xm1, wq, xp1 };

    const float* vp = value + (b * CIN + cbase) * (HV * WV);
    float* op = out + ((b * CIN + cbase) * HO + 2 * h) * WO + 2 * wq;
    const int VCS = HV * WV;                   // 4096
    const int GCS = HO * WO;                   // 16384

#pragma unroll 4
    for (int c = 0; c < 8; ++c) {
        const float* v = vp + c * VCS;
        float nv[K9];
#pragma unroll
        for (int dy = 0; dy < 3; ++dy)
#pragma unroll
            for (int dx = 0; dx < 3; ++dx)
                nv[dy * 3 + dx] = __ldg(v + ro[dy] + co[dx]);

        u64 o0 = 0ull, o1 = 0ull;
#pragma unroll
        for (int k = 0; k < K9; ++k) {
            u64 NV = pk2(nv[k], nv[k]);
            o0 = fma2(acc[k][0], NV, o0);
            o1 = fma2(acc[k][1], NV, o1);
        }
        *(u64*)(op + c * GCS)      = o0;
        *(u64*)(op + c * GCS + WO) = o1;
    }
}

extern "C" void kernel_launch(void* const* d_in, const int* in_sizes, int n_in,
                              void* d_out, int out_size) {
    const float* guide = (const float*)d_in[0];
    const float* value = (const float*)d_in[1];
    const float* wconv = (const float*)d_in[2];
    const float* bconv = (const float*)d_in[3];
    float* out = (float*)d_out;
    (void)in_sizes; (void)n_in; (void)out_size;

    la_att_kernel<<<1024, 128>>>(guide, wconv, bconv);
    la_out_kernel<<<4096, 128>>>(value, out);
}

// round 4
// speedup vs baseline: 1.2674x; 1.1447x over previous
#include <cuda_runtime.h>

// LocalAttender — Round 4: two-kernel split; out-kernel gathers value from
// SMEM-staged rows instead of 9 scalar global loads per channel.
// Shapes (fixed): guide [8,128,128,128] f32, value [8,128,64,64] f32,
//                 w_conv [9,128] f32, b_conv [9] f32, out [8,128,128,128] f32.

#define K9 9
#define CIN 128
#define HV 64
#define WV 64
#define HO 128
#define WO 128

typedef unsigned long long u64;

__device__ u64 g_att[8][64][2][2 * K9][32];   // 4.7 MB scratch

__device__ __forceinline__ u64 pk2(float lo, float hi) {
    u64 d; asm("mov.b64 %0, {%1,%2};" : "=l"(d) : "f"(lo), "f"(hi)); return d;
}
__device__ __forceinline__ void upk2(u64 v, float& lo, float& hi) {
    asm("mov.b64 {%0,%1}, %2;" : "=f"(lo), "=f"(hi) : "l"(v));
}
__device__ __forceinline__ u64 fma2(u64 a, u64 b, u64 c) {
    u64 d; asm("fma.rn.f32x2 %0, %1, %2, %3;" : "=l"(d) : "l"(a), "l"(b), "l"(c)); return d;
}
__device__ __forceinline__ u64 add2(u64 a, u64 b) {
    u64 d; asm("add.rn.f32x2 %0, %1, %2;" : "=l"(d) : "l"(a), "l"(b)); return d;
}

__device__ __forceinline__ void softmax9(float a[K9]) {
    float m = a[0];
#pragma unroll
    for (int k = 1; k < K9; ++k) m = fmaxf(m, a[k]);
    float s = 0.0f;
#pragma unroll
    for (int k = 0; k < K9; ++k) { a[k] = __expf(a[k] - m); s += a[k]; }
    float inv = 1.0f / s;
#pragma unroll
    for (int k = 0; k < K9; ++k) a[k] *= inv;
}

// ---------------------------------------------------------------------------
// Kernel A: att.  Grid = B*H*2 = 1024 blocks, 128 threads.  (unchanged)
// ---------------------------------------------------------------------------
__global__ __launch_bounds__(128, 6)
void la_att_kernel(const float* __restrict__ guide,
                   const float* __restrict__ wconv,
                   const float* __restrict__ bconv) {
    __shared__ u64 w2_s[CIN * K9];
    __shared__ float b_s[K9];
    __shared__ u64 part[4][32][2 * K9 + 1];

    const int tid  = threadIdx.x;
    const int warp = tid >> 5;
    const int lane = tid & 31;

    for (int i = tid; i < CIN * K9; i += 128) {
        int k = i >> 7, c = i & (CIN - 1);
        float v = wconv[i];
        w2_s[c * K9 + k] = pk2(v, v);
    }
    if (tid < K9) b_s[tid] = bconv[tid];
    __syncthreads();

    const int b     = blockIdx.x >> 7;
    const int h     = (blockIdx.x >> 1) & 63;
    const int set   = blockIdx.x & 1;
    const int wq    = (set << 5) + lane;
    const int cbase = warp << 5;

    u64 acc[K9][2];
#pragma unroll
    for (int k = 0; k < K9; ++k) { acc[k][0] = 0ull; acc[k][1] = 0ull; }

    const float* gp = guide + ((b * CIN + cbase) * HO + 2 * h) * WO + 2 * wq;
    const int GCS = HO * WO;

    if (warp == 0) {
#pragma unroll
        for (int c = 0; c < K9; ++c) {
            u64 G0 = *(const u64*)(gp + c * GCS);
            u64 G1 = *(const u64*)(gp + c * GCS + WO);
#pragma unroll
            for (int k = 0; k < K9; ++k) {
                u64 W = w2_s[c * K9 + k];
                acc[k][0] = fma2(G0, W, acc[k][0]);
                acc[k][1] = fma2(G1, W, acc[k][1]);
            }
            acc[c][0] = add2(acc[c][0], G0);   // residual guide[:, :9]
            acc[c][1] = add2(acc[c][1], G1);
        }
#pragma unroll 4
        for (int c = K9; c < 32; ++c) {
            u64 G0 = *(const u64*)(gp + c * GCS);
            u64 G1 = *(const u64*)(gp + c * GCS + WO);
#pragma unroll
            for (int k = 0; k < K9; ++k) {
                u64 W = w2_s[c * K9 + k];
                acc[k][0] = fma2(G0, W, acc[k][0]);
                acc[k][1] = fma2(G1, W, acc[k][1]);
            }
        }
    } else {
#pragma unroll 4
        for (int c = 0; c < 32; ++c) {
            u64 G0 = *(const u64*)(gp + c * GCS);
            u64 G1 = *(const u64*)(gp + c * GCS + WO);
#pragma unroll
            for (int k = 0; k < K9; ++k) {
                u64 W = w2_s[(cbase + c) * K9 + k];
                acc[k][0] = fma2(G0, W, acc[k][0]);
                acc[k][1] = fma2(G1, W, acc[k][1]);
            }
        }
    }

#pragma unroll
    for (int k = 0; k < K9; ++k) {
        part[warp][lane][2 * k]     = acc[k][0];
        part[warp][lane][2 * k + 1] = acc[k][1];
    }
    __syncthreads();
#pragma unroll
    for (int pw = 1; pw < 4; ++pw) {
        const int peer = warp ^ pw;
#pragma unroll
        for (int k = 0; k < K9; ++k) {
            acc[k][0] = add2(acc[k][0], part[peer][lane][2 * k]);
            acc[k][1] = add2(acc[k][1], part[peer][lane][2 * k + 1]);
        }
    }

    if (warp == 0) {
#pragma unroll
        for (int k = 0; k < K9; ++k) {
            u64 B = pk2(b_s[k], b_s[k]);
            acc[k][0] = add2(acc[k][0], B);
            acc[k][1] = add2(acc[k][1], B);
        }
#pragma unroll
        for (int r = 0; r < 2; ++r) {
            float a0[K9], a1[K9];
#pragma unroll
            for (int k = 0; k < K9; ++k) upk2(acc[k][r], a0[k], a1[k]);
            softmax9(a0);
            softmax9(a1);
#pragma unroll
            for (int k = 0; k < K9; ++k) acc[k][r] = pk2(a0[k], a1[k]);
        }
#pragma unroll
        for (int k = 0; k < K9; ++k) {
            g_att[b][h][set][2 * k][lane]     = acc[k][0];
            g_att[b][h][set][2 * k + 1][lane] = acc[k][1];
        }
    }
}

// ---------------------------------------------------------------------------
// Kernel B: output.  Grid = B*H*2*4 = 4096 blocks, 128 threads.
// Block = (b, h, set, channel-group of 32); warp w: channels [8w, 8w+8).
// R4: value rows (clamped h-1, h, h+1; full 64 cols) staged to SMEM once per
// block via float4; the 9-neighbor gather becomes conflict-free LDS.
// ---------------------------------------------------------------------------
__global__ __launch_bounds__(128, 6)
void la_out_kernel(const float* __restrict__ value,
                   float* __restrict__ out) {
    __shared__ float vs[32][3][64];            // 24576 B
    __shared__ u64 att_s[2 * K9 * 32];         // 4608 B

    const int tid  = threadIdx.x;
    const int warp = tid >> 5;
    const int lane = tid & 31;

    const int cg  = blockIdx.x & 3;
    const int set = (blockIdx.x >> 2) & 1;
    const int h   = (blockIdx.x >> 3) & 63;
    const int b   = blockIdx.x >> 9;
    const int cblk = cg << 5;                  // block channel base

    const int ym1 = (h == 0) ? 0 : h - 1;
    const int yp1 = (h == HV - 1) ? HV - 1 : h + 1;

    // stage att (576 u64, coalesced)
    {
        const u64* reg = &g_att[b][h][set][0][0];
        for (int i = tid; i < 2 * K9 * 32; i += 128) att_s[i] = reg[i];
    }

    // stage value: 32 ch x 3 rows x 64 cols as float4 (1536 vec4, 12/thread)
    {
        const float* vbase = value + (b * CIN + cblk) * (HV * WV);
        const int rowoff[3] = { ym1 * WV, h * WV, yp1 * WV };
#pragma unroll
        for (int it = 0; it < 12; ++it) {
            int i   = tid + it * 128;
            int c   = i / 48;
            int rem = i - c * 48;
            int r   = rem >> 4;
            int q   = rem & 15;
            float4 v4 = *(const float4*)(vbase + c * (HV * WV) + rowoff[r] + q * 4);
            *(float4*)&vs[c][r][q * 4] = v4;
        }
    }
    __syncthreads();

    const int wq  = (set << 5) + lane;         // global value col
    const int xm1 = (wq == 0) ? 0 : wq - 1;
    const int xp1 = (wq == WV - 1) ? WV - 1 : wq + 1;
    const int cth = warp << 3;                 // 8 channels per thread

    u64 acc[K9][2];
#pragma unroll
    for (int k = 0; k < K9; ++k) {
        acc[k][0] = att_s[(2 * k) * 32 + lane];
        acc[k][1] = att_s[(2 * k + 1) * 32 + lane];
    }

    float* op = out + ((b * CIN + cblk + cth) * HO + 2 * h) * WO + 2 * wq;
    const int GCS = HO * WO;                   // 16384

#pragma unroll
    for (int c = 0; c < 8; ++c) {
        const float* vr = &vs[cth + c][0][0];
        float nv[K9];
#pragma unroll
        for (int r = 0; r < 3; ++r) {
            nv[r * 3 + 0] = vr[r * 64 + xm1];
            nv[r * 3 + 1] = vr[r * 64 + wq];
            nv[r * 3 + 2] = vr[r * 64 + xp1];
        }
        u64 o0 = 0ull, o1 = 0ull;
#pragma unroll
        for (int k = 0; k < K9; ++k) {
            u64 NV = pk2(nv[k], nv[k]);
            o0 = fma2(acc[k][0], NV, o0);
            o1 = fma2(acc[k][1], NV, o1);
        }
        *(u64*)(op + c * GCS)      = o0;
        *(u64*)(op + c * GCS + WO) = o1;
    }
}

extern "C" void kernel_launch(void* const* d_in, const int* in_sizes, int n_in,
                              void* d_out, int out_size) {
    const float* guide = (const float*)d_in[0];
    const float* value = (const float*)d_in[1];
    const float* wconv = (const float*)d_in[2];
    const float* bconv = (const float*)d_in[3];
    float* out = (float*)d_out;
    (void)in_sizes; (void)n_in; (void)out_size;

    la_att_kernel<<<1024, 128>>>(guide, wconv, bconv);
    la_out_kernel<<<4096, 128>>>(value, out);
}